// round 15
// baseline (speedup 1.0000x reference)
#include <cuda_runtime.h>
#include <cuda_fp16.h>
#include <math.h>
#include <stdint.h>

// ---------------- problem constants ----------------
#define NB    4
#define SEQ   1024
#define HDIM  1024
#define NHEAD 16
#define HEADD 64
#define NLAYER 12
#define MLPD  4096
#define DESM  1280
#define NROWS (NB*SEQ)   // 4096
#define NVOC  26

// ---------------- scratch (static device; no allocs allowed) ----------------
__device__ float  g_x   [NROWS*HDIM];
__device__ float  g_h   [NROWS*HDIM];      // fp32 (final head path)
__device__ __half g_h16 [NROWS*HDIM];      // fp16 ln-mod output (GEMM A)
__device__ __half g_qkv16[NROWS*3*HDIM];   // fp16 qkv
__device__ __half g_o16 [NROWS*HDIM];      // fp16 attention output
__device__ __half g_mid16[NROWS*MLPD];     // fp16 gelu output
__device__ float  g_tsin[NB*256];
__device__ float  g_lsin[NB*128];
__device__ float  g_tb  [NB*HDIM];
__device__ float  g_temb[NB*HDIM];
__device__ float  g_lb  [NB*HDIM];
__device__ float  g_lemb[NB*HDIM];
__device__ float  g_csilu[NB*HDIM];
__device__ float  g_modsAll[NLAYER*NB*6*HDIM];
__device__ float  g_fmods[NB*2*HDIM];
__device__ float  g_ropec[SEQ*32];
__device__ float  g_ropes[SEQ*32];

// fp16 pre-converted GEMM operands (row-major)
__device__ __half g_xt16  [NROWS*DESM];
__device__ __half g_w_proj[DESM*HDIM];
__device__ __half g_w_qkv [NLAYER*HDIM*3*HDIM];
__device__ __half g_w_ap  [NLAYER*HDIM*HDIM];
__device__ __half g_w_m1  [NLAYER*HDIM*MLPD];
__device__ __half g_w_m2  [NLAYER*MLPD*HDIM];

// ---------------- small helpers ----------------
__device__ __forceinline__ float siluf(float x){ return x / (1.0f + __expf(-x)); }
__device__ __forceinline__ float geluf(float x){
    float u = 0.7978845608028654f*(x + 0.044715f*x*x*x);
    float t = 1.0f - 2.0f/(__expf(2.0f*u) + 1.0f);
    return 0.5f*x*(1.0f + t);
}
__device__ __forceinline__ uint32_t smem_u32(const void* p){
    return (uint32_t)__cvta_generic_to_shared(p);
}
__device__ __forceinline__ uint32_t h2pack(float a, float b){
    __half2 h = __floats2half2_rn(a, b);
    return *(uint32_t*)&h;
}
__device__ __forceinline__ void ldsm_x4(uint32_t& r0, uint32_t& r1, uint32_t& r2,
                                        uint32_t& r3, uint32_t addr)
{
    asm volatile("ldmatrix.sync.aligned.m8n8.x4.shared.b16 {%0,%1,%2,%3}, [%4];"
                 : "=r"(r0), "=r"(r1), "=r"(r2), "=r"(r3) : "r"(addr));
}
__device__ __forceinline__ void ldsm_x4t(uint32_t& r0, uint32_t& r1, uint32_t& r2,
                                         uint32_t& r3, uint32_t addr)
{
    asm volatile("ldmatrix.sync.aligned.m8n8.x4.trans.shared.b16 {%0,%1,%2,%3}, [%4];"
                 : "=r"(r0), "=r"(r1), "=r"(r2), "=r"(r3) : "r"(addr));
}
__device__ __forceinline__ void ldsm_x2t(uint32_t& r0, uint32_t& r1, uint32_t addr)
{
    asm volatile("ldmatrix.sync.aligned.m8n8.x2.trans.shared.b16 {%0,%1}, [%2];"
                 : "=r"(r0), "=r"(r1) : "r"(addr));
}
__device__ __forceinline__ void mma_f16(float& d0, float& d1, float& d2, float& d3,
    uint32_t a0, uint32_t a1, uint32_t a2, uint32_t a3, uint32_t b0, uint32_t b1)
{
    asm volatile("mma.sync.aligned.m16n8k16.row.col.f32.f16.f16.f32 "
        "{%0,%1,%2,%3}, {%4,%5,%6,%7}, {%8,%9}, {%0,%1,%2,%3};"
        : "+f"(d0), "+f"(d1), "+f"(d2), "+f"(d3)
        : "r"(a0), "r"(a1), "r"(a2), "r"(a3), "r"(b0), "r"(b1));
}

// ---------------- fp32 -> fp16 conversion (2-way unrolled grid-stride) ------
__global__ void f16_conv_kernel(const float4* __restrict__ src,
                                uint2* __restrict__ dst, int n4)
{
    int i = blockIdx.x*blockDim.x + threadIdx.x;
    int stride = gridDim.x*blockDim.x;
    for (; i < n4; i += 2*stride) {
        float4 v0 = src[i];
        int i1 = i + stride;
        float4 v1;
        bool ok1 = (i1 < n4);
        if (ok1) v1 = src[i1];
        uint2 u0;
        u0.x = h2pack(v0.x, v0.y);
        u0.y = h2pack(v0.z, v0.w);
        dst[i] = u0;
        if (ok1) {
            uint2 u1;
            u1.x = h2pack(v1.x, v1.y);
            u1.y = h2pack(v1.z, v1.w);
            dst[i1] = u1;
        }
    }
}

// ---------------- embeddings ----------------
__global__ void embed_kernel(const int* __restrict__ t, const int* __restrict__ Lt,
                             const int* __restrict__ Tv)
{
    int b = blockIdx.x;
    int i = threadIdx.x; // 128 threads
    float tn = (float)t[b] / (float)Tv[0];
    float f = expf(-logf(10000.0f) * (float)i / 128.0f);
    float a = tn * f;
    g_tsin[b*256 + i]       = cosf(a);
    g_tsin[b*256 + 128 + i] = sinf(a);
    if (i < 64) {
        float fl = expf(-logf(10000.0f) * (float)i / 64.0f);
        float al = (float)Lt[b] * fl;
        g_lsin[b*128 + i]      = cosf(al);
        g_lsin[b*128 + 64 + i] = sinf(al);
    }
}

__global__ void smallmm_kernel(const float* __restrict__ in, const float* __restrict__ w,
                               const float* __restrict__ bias, float* __restrict__ out,
                               int M, int K, int N, int act)
{
    int idx = blockIdx.x*blockDim.x + threadIdx.x;
    if (idx >= M*N) return;
    int m = idx / N, n = idx % N;
    float s = bias[n];
    const float* ip = in + (size_t)m*K;
    const float* wp = w + n;
    for (int k = 0; k < K; k += 4) {
        float4 iv = *(const float4*)(ip + k);
        s += iv.x * wp[(size_t)(k+0)*N];
        s += iv.y * wp[(size_t)(k+1)*N];
        s += iv.z * wp[(size_t)(k+2)*N];
        s += iv.w * wp[(size_t)(k+3)*N];
    }
    if (act == 1) s = siluf(s);
    out[idx] = s;
}

// all-layer adaLN mods: one thread per (layer, n), computes all 4 batches
// from a single weight stream (4x less L2/DRAM traffic than per-batch form).
// Accumulation order per output identical to previous version (sequential k).
__global__ void ada_all_kernel(const float* __restrict__ aw, const float* __restrict__ ab)
{
    int idx = blockIdx.x*blockDim.x + threadIdx.x;
    if (idx >= NLAYER*6*HDIM) return;
    int n = idx % (6*HDIM);
    int l = idx / (6*HDIM);
    const float* w  = aw + (size_t)l*HDIM*6*HDIM + n;
    const float* c0 = g_csilu;
    const float* c1 = g_csilu + HDIM;
    const float* c2 = g_csilu + 2*HDIM;
    const float* c3 = g_csilu + 3*HDIM;
    float bias = ab[l*6*HDIM + n];
    float s0 = bias, s1 = bias, s2 = bias, s3 = bias;
    #pragma unroll 4
    for (int k = 0; k < HDIM; k++) {
        float wv = w[(size_t)k*6*HDIM];
        s0 += c0[k]*wv;
        s1 += c1[k]*wv;
        s2 += c2[k]*wv;
        s3 += c3[k]*wv;
    }
    size_t base = (size_t)l*NB*6*HDIM + n;
    g_modsAll[base + 0*6*HDIM] = s0;
    g_modsAll[base + 1*6*HDIM] = s1;
    g_modsAll[base + 2*6*HDIM] = s2;
    g_modsAll[base + 3*6*HDIM] = s3;
}

__global__ void csilu_kernel()
{
    int idx = blockIdx.x*blockDim.x + threadIdx.x;
    if (idx >= NB*HDIM) return;
    float c = g_temb[idx] + g_lemb[idx];
    g_csilu[idx] = siluf(c);
}

__global__ void rope_table_kernel()
{
    int idx = blockIdx.x*blockDim.x + threadIdx.x;
    if (idx >= SEQ*32) return;
    int pos = idx >> 5, m = idx & 31;
    float f = expf(-logf(10000.0f) * (float)(2*m) / 64.0f);
    float a = (float)pos * f;
    g_ropec[idx] = cosf(a);
    g_ropes[idx] = sinf(a);
}

// ---------------- layernorm + modulate (warp-per-row, no smem/barriers) -----
__global__ void __launch_bounds__(256) ln_mod_kernel(const float* __restrict__ x,
                                                     const float* __restrict__ mods,
                                                     int mstride, int sh_off, int sc_off,
                                                     void* __restrict__ outv, int fmt16)
{
    int row  = (blockIdx.x*blockDim.x + threadIdx.x) >> 5;
    int lane = threadIdx.x & 31;
    int b    = row >> 10;
    const float* xr = x + (size_t)row*HDIM;

    float4 v[8];
    float s = 0.0f;
    #pragma unroll
    for (int i = 0; i < 8; i++) {
        v[i] = *(const float4*)(xr + lane*4 + i*128);
        s += v[i].x + v[i].y + v[i].z + v[i].w;
    }
    #pragma unroll
    for (int off = 16; off > 0; off >>= 1) s += __shfl_xor_sync(0xffffffffu, s, off);
    float mu = s * (1.0f/1024.0f);

    float q = 0.0f;
    #pragma unroll
    for (int i = 0; i < 8; i++) {
        v[i].x -= mu; v[i].y -= mu; v[i].z -= mu; v[i].w -= mu;
        q += v[i].x*v[i].x + v[i].y*v[i].y + v[i].z*v[i].z + v[i].w*v[i].w;
    }
    #pragma unroll
    for (int off = 16; off > 0; off >>= 1) q += __shfl_xor_sync(0xffffffffu, q, off);
    float rs = rsqrtf(q * (1.0f/1024.0f) + 1e-6f);

    const float* mb = mods + (size_t)b*mstride;
    #pragma unroll
    for (int i = 0; i < 8; i++) {
        int c = lane*4 + i*128;
        float4 sc = *(const float4*)(mb + sc_off + c);
        float4 sh = *(const float4*)(mb + sh_off + c);
        float o0 = v[i].x*rs*(1.0f+sc.x) + sh.x;
        float o1 = v[i].y*rs*(1.0f+sc.y) + sh.y;
        float o2 = v[i].z*rs*(1.0f+sc.z) + sh.z;
        float o3 = v[i].w*rs*(1.0f+sc.w) + sh.w;
        if (fmt16) {
            uint2 u; u.x = h2pack(o0, o1); u.y = h2pack(o2, o3);
            *(uint2*)((__half*)outv + (size_t)row*HDIM + c) = u;
        } else {
            *(float4*)((float*)outv + (size_t)row*HDIM + c) = make_float4(o0,o1,o2,o3);
        }
    }
}

// ---------------- fp16 tensor-core GEMM (exact R9 structure) ----------------
// MODE 0: C(fp32) = acc + bias
// MODE 1: C(fp16) = gelu(acc + bias)
// MODE 2: C(fp32) = resid + gate * (acc + bias)
// MODE 3: C(fp16) = acc + bias
template<int MODE>
__global__ void __launch_bounds__(256, 2) gemm_f16_kernel(
    const __half* __restrict__ A, const __half* __restrict__ W,
    const float* __restrict__ bias, void* __restrict__ Cv,
    int M, int N, int K,
    const float* __restrict__ resid, const float* __restrict__ gate,
    int g_off, int g_stride)
{
    __shared__ __align__(16) __half As[2][4096];
    __shared__ __align__(16) __half Bs[2][4096];

    const int tid = threadIdx.x;
    const int ln  = tid & 31;
    const int wp  = tid >> 5;
    const int wm  = wp >> 2;
    const int wn  = wp & 3;
    const int bm  = blockIdx.y * 128, bn = blockIdx.x * 128;

    float acc[4][4][4];
    #pragma unroll
    for (int i = 0; i < 4; i++)
        #pragma unroll
        for (int j = 0; j < 4; j++)
            #pragma unroll
            for (int c = 0; c < 4; c++) acc[i][j][c] = 0.0f;

    const int idA0 = tid, idA1 = tid + 256;
    const int arA0 = idA0 >> 2, tkA0 = idA0 & 3;
    const int arA1 = idA1 >> 2, tkA1 = idA1 & 3;
    const int brB0 = idA0 >> 4, ntB0 = idA0 & 15;
    const int brB1 = idA1 >> 4, ntB1 = idA1 & 15;

    uint4 pa[2], pb[2];
    const int nkt = K >> 5;

    pa[0] = *(const uint4*)(A + (size_t)(bm+arA0)*K + tkA0*8);
    pa[1] = *(const uint4*)(A + (size_t)(bm+arA1)*K + tkA1*8);
    pb[0] = *(const uint4*)(W + (size_t)brB0*N + bn + ntB0*8);
    pb[1] = *(const uint4*)(W + (size_t)brB1*N + bn + ntB1*8);

    #define STORE_TILE(BUF)                                                      \
    {                                                                            \
        {   int tile = ((arA0>>3)<<2) + tkA0;                                    \
            int row  = (arA0&7) ^ ((tkA0<<1)&7);                                 \
            *(uint4*)&As[BUF][tile*64 + row*8] = pa[0];                          \
            tile = ((arA1>>3)<<2) + tkA1;                                        \
            row  = (arA1&7) ^ ((tkA1<<1)&7);                                     \
            *(uint4*)&As[BUF][tile*64 + row*8] = pa[1];                          \
            tile = ((brB0>>3)<<4) + ntB0;                                        \
            row  = (brB0&7) ^ (ntB0&7);                                          \
            *(uint4*)&Bs[BUF][tile*64 + row*8] = pb[0];                          \
            tile = ((brB1>>3)<<4) + ntB1;                                        \
            row  = (brB1&7) ^ (ntB1&7);                                          \
            *(uint4*)&Bs[BUF][tile*64 + row*8] = pb[1];                          \
        }                                                                        \
    }

    STORE_TILE(0);
    __syncthreads();

    for (int kt = 0; kt < nkt; kt++) {
        const int cur = kt & 1;
        if (kt + 1 < nkt) {
            const __half* Ak = A + (size_t)(kt+1)*32;
            const __half* Wk = W + (size_t)(kt+1)*32*N;
            pa[0] = *(const uint4*)(Ak + (size_t)(bm+arA0)*K + tkA0*8);
            pa[1] = *(const uint4*)(Ak + (size_t)(bm+arA1)*K + tkA1*8);
            pb[0] = *(const uint4*)(Wk + (size_t)brB0*N + bn + ntB0*8);
            pb[1] = *(const uint4*)(Wk + (size_t)brB1*N + bn + ntB1*8);
        }

        #pragma unroll
        for (int s = 0; s < 2; s++) {
            uint32_t a[4][4], b[4][2];
            const int sel = ln >> 3, tmo = sel & 1, tko_a = sel >> 1;
            const int tkA = 2*s + tko_a;
            const int rowA = (ln&7) ^ ((tkA<<1)&7);
            #pragma unroll
            for (int i = 0; i < 4; i++) {
                int tmb = wm*8 + i*2;
                int tile = (tmb + tmo)*4 + tkA;
                ldsm_x4(a[i][0], a[i][1], a[i][2], a[i][3],
                        smem_u32(&As[cur][tile*64 + rowA*8]));
            }
            const int lnm = ln & 15;
            const int tkB = 2*s + (lnm >> 3);
            #pragma unroll
            for (int j = 0; j < 4; j++) {
                int nt = wn*4 + j;
                int tile = tkB*16 + nt;
                int rowB = (lnm&7) ^ (nt&7);
                ldsm_x2t(b[j][0], b[j][1],
                         smem_u32(&Bs[cur][tile*64 + rowB*8]));
            }
            #pragma unroll
            for (int i = 0; i < 4; i++)
                #pragma unroll
                for (int j = 0; j < 4; j++)
                    mma_f16(acc[i][j][0],acc[i][j][1],acc[i][j][2],acc[i][j][3],
                            a[i][0],a[i][1],a[i][2],a[i][3], b[j][0],b[j][1]);
        }

        if (kt + 1 < nkt) STORE_TILE(cur ^ 1);
        __syncthreads();
    }
    #undef STORE_TILE

    float*  C   = (float*)Cv;
    __half* C16 = (__half*)Cv;
    const int g0 = ln >> 2, t0 = ln & 3;
    #pragma unroll
    for (int i = 0; i < 4; i++) {
        int m0 = bm + wm*64 + i*16 + g0;
        int m1 = m0 + 8;
        #pragma unroll
        for (int j = 0; j < 4; j++) {
            int n0 = bn + wn*32 + j*8 + t0*2;
            float2 bv = *(const float2*)(bias + n0);
            float v00 = acc[i][j][0] + bv.x;
            float v01 = acc[i][j][1] + bv.y;
            float v10 = acc[i][j][2] + bv.x;
            float v11 = acc[i][j][3] + bv.y;
            if (MODE == 1 || MODE == 3) {
                if (MODE == 1) { v00=geluf(v00); v01=geluf(v01); v10=geluf(v10); v11=geluf(v11); }
                uint32_t h0 = h2pack(v00, v01);
                uint32_t h1 = h2pack(v10, v11);
                *(uint32_t*)(C16 + (size_t)m0*N + n0) = h0;
                *(uint32_t*)(C16 + (size_t)m1*N + n0) = h1;
            } else {
                if (MODE == 2) {
                    float2 gv0 = *(const float2*)(gate + (size_t)(m0 >> 10)*g_stride + g_off + n0);
                    float2 gv1 = *(const float2*)(gate + (size_t)(m1 >> 10)*g_stride + g_off + n0);
                    float2 r0 = *(const float2*)(resid + (size_t)m0*N + n0);
                    float2 r1 = *(const float2*)(resid + (size_t)m1*N + n0);
                    v00 = r0.x + gv0.x*v00;  v01 = r0.y + gv0.y*v01;
                    v10 = r1.x + gv1.x*v10;  v11 = r1.y + gv1.y*v11;
                }
                *(float2*)(C + (size_t)m0*N + n0) = make_float2(v00, v01);
                *(float2*)(C + (size_t)m1*N + n0) = make_float2(v10, v11);
            }
        }
    }
}

// ---------------- fp16 tensor-core flash attention, BQ=128, 8 warps ----------
__global__ void __launch_bounds__(256) flash16_kernel(const __half* __restrict__ qkv,
                                                      __half* __restrict__ o)
{
    __shared__ __align__(16) __half Qs[8192];   // 128 x 64
    __shared__ __align__(16) __half Ks[4096];   // 64 x 64
    __shared__ __align__(16) __half Vs[4096];   // 64 x 64

    const int tid = threadIdx.x;
    const int ln  = tid & 31;
    const int w   = tid >> 5;                   // 0..7
    const int qt = blockIdx.x, h = blockIdx.y, b = blockIdx.z;
    const __half* base = qkv + (size_t)b*SEQ*3*HDIM + h*HEADD;

    const int g  = ln >> 3, rr = ln & 7;

    #pragma unroll
    for (int it = 0; it < 4; it++) {
        int id = tid + it*256;
        int pl = id >> 3;          // 0..127
        int ch = id & 7;
        int pos = qt*128 + pl;
        uint4 raw = *(const uint4*)(base + (size_t)pos*3*HDIM + ch*8);
        __half2* hp = (__half2*)&raw;
        int ci = pos*32 + ((ch&3)*8);
        float4 c0 = *(const float4*)(g_ropec + ci);
        float4 c1 = *(const float4*)(g_ropec + ci + 4);
        float4 s0 = *(const float4*)(g_ropes + ci);
        float4 s1 = *(const float4*)(g_ropes + ci + 4);
        float cc[8] = {c0.x,c0.y,c0.z,c0.w,c1.x,c1.y,c1.z,c1.w};
        float ss[8] = {s0.x,s0.y,s0.z,s0.w,s1.x,s1.y,s1.z,s1.w};
        uint4 outv;
        uint32_t* op = (uint32_t*)&outv;
        #pragma unroll
        for (int e = 0; e < 4; e++) {
            float x1 = __low2float(hp[e]), x2 = __high2float(hp[e]);
            float r1 = (x1*cc[2*e]   - x2*ss[2*e])  *0.125f;
            float r2 = (x2*cc[2*e+1] + x1*ss[2*e+1])*0.125f;
            op[e] = h2pack(r1, r2);
        }
        *(uint4*)&Qs[((pl>>3)*8 + ch)*64 + ((pl&7)^ch)*8] = outv;
    }

    float m_i[2], l_i[2], oa[8][4];
    m_i[0] = m_i[1] = -1e30f; l_i[0] = l_i[1] = 0.0f;
    #pragma unroll
    for (int j = 0; j < 8; j++)
        #pragma unroll
        for (int c = 0; c < 4; c++) oa[j][c] = 0.0f;

    for (int kt = 0; kt < SEQ/64; kt++) {
        __syncthreads();
        #pragma unroll
        for (int it = 0; it < 2; it++) {
            int id = tid + it*256;
            int pl = id >> 3;      // 0..63
            int ch = id & 7;
            int pos = kt*64 + pl;
            const __half* rowp = base + (size_t)pos*3*HDIM;
            uint4 raw = *(const uint4*)(rowp + HDIM + ch*8);
            __half2* hp = (__half2*)&raw;
            int ci = pos*32 + ((ch&3)*8);
            float4 c0 = *(const float4*)(g_ropec + ci);
            float4 c1 = *(const float4*)(g_ropec + ci + 4);
            float4 s0 = *(const float4*)(g_ropes + ci);
            float4 s1 = *(const float4*)(g_ropes + ci + 4);
            float cc[8] = {c0.x,c0.y,c0.z,c0.w,c1.x,c1.y,c1.z,c1.w};
            float ss[8] = {s0.x,s0.y,s0.z,s0.w,s1.x,s1.y,s1.z,s1.w};
            uint4 outv;
            uint32_t* op = (uint32_t*)&outv;
            #pragma unroll
            for (int e = 0; e < 4; e++) {
                float x1 = __low2float(hp[e]), x2 = __high2float(hp[e]);
                float r1 = x1*cc[2*e]   - x2*ss[2*e];
                float r2 = x2*cc[2*e+1] + x1*ss[2*e+1];
                op[e] = h2pack(r1, r2);
            }
            int dst = ((pl>>3)*8 + ch)*64 + ((pl&7)^ch)*8;
            *(uint4*)&Ks[dst] = outv;
            *(uint4*)&Vs[dst] = *(const uint4*)(rowp + 2*HDIM + ch*8);
        }
        __syncthreads();

        float sacc[8][4];
        #pragma unroll
        for (int j = 0; j < 8; j++)
            #pragma unroll
            for (int c = 0; c < 4; c++) sacc[j][c] = 0.0f;

        #pragma unroll
        for (int ks = 0; ks < 4; ks++) {
            const int dt0 = ks*2;
            uint32_t a0,a1,a2,a3;
            {
                int pt = w*2 + (g&1), dt = dt0 + (g>>1);
                ldsm_x4(a0,a1,a2,a3,
                        smem_u32(&Qs[(pt*8+dt)*64 + (rr^dt)*8]));
            }
            #pragma unroll
            for (int nb2 = 0; nb2 < 4; nb2++) {
                uint32_t b0,b1,b2,b3;
                int pt = nb2*2 + (g>>1), dt = dt0 + (g&1);
                ldsm_x4(b0,b1,b2,b3,
                        smem_u32(&Ks[(pt*8+dt)*64 + (rr^dt)*8]));
                mma_f16(sacc[nb2*2][0],sacc[nb2*2][1],sacc[nb2*2][2],sacc[nb2*2][3],
                        a0,a1,a2,a3, b0,b1);
                mma_f16(sacc[nb2*2+1][0],sacc[nb2*2+1][1],sacc[nb2*2+1][2],sacc[nb2*2+1][3],
                        a0,a1,a2,a3, b2,b3);
            }
        }

        float mx0 = -1e30f, mx1 = -1e30f;
        #pragma unroll
        for (int j = 0; j < 8; j++) {
            mx0 = fmaxf(mx0, fmaxf(sacc[j][0], sacc[j][1]));
            mx1 = fmaxf(mx1, fmaxf(sacc[j][2], sacc[j][3]));
        }
        mx0 = fmaxf(mx0, __shfl_xor_sync(0xffffffffu, mx0, 1));
        mx0 = fmaxf(mx0, __shfl_xor_sync(0xffffffffu, mx0, 2));
        mx1 = fmaxf(mx1, __shfl_xor_sync(0xffffffffu, mx1, 1));
        mx1 = fmaxf(mx1, __shfl_xor_sync(0xffffffffu, mx1, 2));
        float mn0 = fmaxf(m_i[0], mx0), mn1 = fmaxf(m_i[1], mx1);
        float al0 = __expf(m_i[0] - mn0), al1 = __expf(m_i[1] - mn1);
        float sum0 = 0.0f, sum1 = 0.0f;
        #pragma unroll
        for (int j = 0; j < 8; j++) {
            sacc[j][0] = __expf(sacc[j][0] - mn0);
            sacc[j][1] = __expf(sacc[j][1] - mn0);
            sacc[j][2] = __expf(sacc[j][2] - mn1);
            sacc[j][3] = __expf(sacc[j][3] - mn1);
            sum0 += sacc[j][0] + sacc[j][1];
            sum1 += sacc[j][2] + sacc[j][3];
        }
        sum0 += __shfl_xor_sync(0xffffffffu, sum0, 1);
        sum0 += __shfl_xor_sync(0xffffffffu, sum0, 2);
        sum1 += __shfl_xor_sync(0xffffffffu, sum1, 1);
        sum1 += __shfl_xor_sync(0xffffffffu, sum1, 2);
        l_i[0] = l_i[0]*al0 + sum0;
        l_i[1] = l_i[1]*al1 + sum1;
        m_i[0] = mn0; m_i[1] = mn1;
        #pragma unroll
        for (int j = 0; j < 8; j++) {
            oa[j][0] *= al0; oa[j][1] *= al0;
            oa[j][2] *= al1; oa[j][3] *= al1;
        }

        uint32_t pf[8][2];
        #pragma unroll
        for (int j = 0; j < 8; j++) {
            pf[j][0] = h2pack(sacc[j][0], sacc[j][1]);
            pf[j][1] = h2pack(sacc[j][2], sacc[j][3]);
        }

        #pragma unroll
        for (int ks = 0; ks < 4; ks++) {
            const int pt0 = ks*2;
            uint32_t a0 = pf[2*ks][0], a1 = pf[2*ks][1];
            uint32_t a2 = pf[2*ks+1][0], a3 = pf[2*ks+1][1];
            #pragma unroll
            for (int nb2 = 0; nb2 < 4; nb2++) {
                uint32_t b0,b1,b2,b3;
                int pt = pt0 + (g&1), dt = nb2*2 + (g>>1);
                ldsm_x4t(b0,b1,b2,b3,
                         smem_u32(&Vs[(pt*8+dt)*64 + (rr^dt)*8]));
                mma_f16(oa[nb2*2][0],oa[nb2*2][1],oa[nb2*2][2],oa[nb2*2][3],
                        a0,a1,a2,a3, b0,b1);
                mma_f16(oa[nb2*2+1][0],oa[nb2*2+1][1],oa[nb2*2+1][2],oa[nb2*2+1][3],
                        a0,a1,a2,a3, b2,b3);
            }
        }
    }

    float inv0 = 1.0f / l_i[0], inv1 = 1.0f / l_i[1];
    int r0 = b*SEQ + qt*128 + w*16 + (ln>>2);
    int r1 = r0 + 8;
    __half* ob = o + h*HEADD;
    #pragma unroll
    for (int j = 0; j < 8; j++) {
        int col = j*8 + (ln&3)*2;
        *(uint32_t*)(ob + (size_t)r0*HDIM + col) = h2pack(oa[j][0]*inv0, oa[j][1]*inv0);
        *(uint32_t*)(ob + (size_t)r1*HDIM + col) = h2pack(oa[j][2]*inv1, oa[j][3]*inv1);
    }
}

// ---------------- host side ----------------
static void* symaddr(const void* sym)
{
    void* p = nullptr;
    cudaGetSymbolAddress(&p, sym);
    return p;
}

static void f16_conv(const float* src, __half* dst, size_t n)
{
    int n4 = (int)(n >> 2);
    int grid = (n4 + 511)/512; if (grid > 4096) grid = 4096;
    f16_conv_kernel<<<grid, 256>>>((const float4*)src, (uint2*)dst, n4);
}

extern "C" void kernel_launch(void* const* d_in, const int* in_sizes, int n_in,
                              void* d_out, int out_size)
{
    const float* x_tokens  = (const float*)d_in[0];
    const int*   L_target  = (const int*)  d_in[1];
    const int*   t_in      = (const int*)  d_in[2];
    const int*   T_in      = (const int*)  d_in[3];
    const float* proj_in_w = (const float*)d_in[4];
    const float* proj_in_b = (const float*)d_in[5];
    const float* t_w1 = (const float*)d_in[6];
    const float* t_b1 = (const float*)d_in[7];
    const float* t_w2 = (const float*)d_in[8];
    const float* t_b2 = (const float*)d_in[9];
    const float* l_w1 = (const float*)d_in[10];
    const float* l_b1 = (const float*)d_in[11];
    const float* l_w2 = (const float*)d_in[12];
    const float* l_b2 = (const float*)d_in[13];
    const float* qkv_w = (const float*)d_in[14];
    const float* qkv_b = (const float*)d_in[15];
    const float* attn_proj_w = (const float*)d_in[16];
    const float* attn_proj_b = (const float*)d_in[17];
    const float* mlp_w1 = (const float*)d_in[18];
    const float* mlp_b1 = (const float*)d_in[19];
    const float* mlp_w2 = (const float*)d_in[20];
    const float* mlp_b2 = (const float*)d_in[21];
    const float* ada_w  = (const float*)d_in[22];
    const float* ada_b  = (const float*)d_in[23];
    const float* fin_ada_w = (const float*)d_in[24];
    const float* fin_ada_b = (const float*)d_in[25];
    const float* fin_w = (const float*)d_in[26];
    const float* fin_b = (const float*)d_in[27];
    float* out = (float*)d_out;

    float*  px    = (float*) symaddr(g_x);
    float*  ph    = (float*) symaddr(g_h);
    __half* ph16  = (__half*)symaddr(g_h16);
    __half* pqkv16= (__half*)symaddr(g_qkv16);
    __half* po16  = (__half*)symaddr(g_o16);
    __half* pmid16= (__half*)symaddr(g_mid16);
    float*  ptsin = (float*) symaddr(g_tsin);
    float*  plsin = (float*) symaddr(g_lsin);
    float*  ptb   = (float*) symaddr(g_tb);
    float*  ptemb = (float*) symaddr(g_temb);
    float*  plb   = (float*) symaddr(g_lb);
    float*  plemb = (float*) symaddr(g_lemb);
    float*  pcs   = (float*) symaddr(g_csilu);
    float*  pmodsAll = (float*)symaddr(g_modsAll);
    float*  pfmods= (float*) symaddr(g_fmods);
    __half* pxt16 = (__half*)symaddr(g_xt16);
    __half* pwproj= (__half*)symaddr(g_w_proj);
    __half* pwqkv = (__half*)symaddr(g_w_qkv);
    __half* pwap  = (__half*)symaddr(g_w_ap);
    __half* pwm1  = (__half*)symaddr(g_w_m1);
    __half* pwm2  = (__half*)symaddr(g_w_m2);

    // ---- pre-convert fp16 GEMM operands ----
    f16_conv(x_tokens,    pxt16, (size_t)NROWS*DESM);
    f16_conv(proj_in_w,   pwproj,(size_t)DESM*HDIM);
    f16_conv(qkv_w,       pwqkv, (size_t)NLAYER*HDIM*3*HDIM);
    f16_conv(attn_proj_w, pwap,  (size_t)NLAYER*HDIM*HDIM);
    f16_conv(mlp_w1,      pwm1,  (size_t)NLAYER*HDIM*MLPD);
    f16_conv(mlp_w2,      pwm2,  (size_t)NLAYER*MLPD*HDIM);

    // ---- conditioning path ----
    embed_kernel<<<NB, 128>>>(t_in, L_target, T_in);
    smallmm_kernel<<<(NB*HDIM+255)/256, 256>>>(ptsin, t_w1, t_b1, ptb,   NB, 256,  HDIM, 1);
    smallmm_kernel<<<(NB*HDIM+255)/256, 256>>>(ptb,   t_w2, t_b2, ptemb, NB, HDIM, HDIM, 0);
    smallmm_kernel<<<(NB*HDIM+255)/256, 256>>>(plsin, l_w1, l_b1, plb,   NB, 128,  HDIM, 1);
    smallmm_kernel<<<(NB*HDIM+255)/256, 256>>>(plb,   l_w2, l_b2, plemb, NB, HDIM, HDIM, 0);
    csilu_kernel<<<(NB*HDIM+255)/256, 256>>>();
    rope_table_kernel<<<(SEQ*32+255)/256, 256>>>();
    ada_all_kernel<<<(NLAYER*6*HDIM+255)/256, 256>>>(ada_w, ada_b);

    // ---- input projection ----
    gemm_f16_kernel<0><<<dim3(HDIM/128, NROWS/128), 256>>>(
        pxt16, pwproj, proj_in_b, px, NROWS, HDIM, DESM,
        nullptr, nullptr, 0, 0);

    // ---- transformer blocks ----
    for (int l = 0; l < NLAYER; l++) {
        float* pmods = pmodsAll + (size_t)l*NB*6*HDIM;

        // --- attention half ---
        ln_mod_kernel<<<NROWS/8, 256>>>(px, pmods, 6*HDIM, 0, HDIM, ph16, 1);
        gemm_f16_kernel<3><<<dim3(3*HDIM/128, NROWS/128), 256>>>(
            ph16, pwqkv + (size_t)l*HDIM*3*HDIM, qkv_b + (size_t)l*3*HDIM, pqkv16,
            NROWS, 3*HDIM, HDIM, nullptr, nullptr, 0, 0);
        flash16_kernel<<<dim3(SEQ/128, NHEAD, NB), 256>>>(pqkv16, po16);
        gemm_f16_kernel<2><<<dim3(HDIM/128, NROWS/128), 256>>>(
            po16, pwap + (size_t)l*HDIM*HDIM, attn_proj_b + (size_t)l*HDIM, px,
            NROWS, HDIM, HDIM, px, pmods, 2*HDIM, 6*HDIM);

        // --- mlp half ---
        ln_mod_kernel<<<NROWS/8, 256>>>(px, pmods, 6*HDIM, 3*HDIM, 4*HDIM, ph16, 1);
        gemm_f16_kernel<1><<<dim3(MLPD/128, NROWS/128), 256>>>(
            ph16, pwm1 + (size_t)l*HDIM*MLPD, mlp_b1 + (size_t)l*MLPD, pmid16,
            NROWS, MLPD, HDIM, nullptr, nullptr, 0, 0);
        gemm_f16_kernel<2><<<dim3(HDIM/128, NROWS/128), 256>>>(
            pmid16, pwm2 + (size_t)l*MLPD*HDIM, mlp_b2 + (size_t)l*HDIM, px,
            NROWS, HDIM, MLPD, px, pmods, 5*HDIM, 6*HDIM);
    }

    // ---- final head ----
    smallmm_kernel<<<(NB*2*HDIM+255)/256, 256>>>(pcs, fin_ada_w, fin_ada_b, pfmods,
                                                 NB, HDIM, 2*HDIM, 0);
    ln_mod_kernel<<<NROWS/8, 256>>>(px, pfmods, 2*HDIM, 0, HDIM, ph, 0);
    smallmm_kernel<<<(NROWS*NVOC+255)/256, 256>>>(ph, fin_w, fin_b, out,
                                                  NROWS, HDIM, NVOC, 0);
}

// round 16
// speedup vs baseline: 1.0152x; 1.0152x over previous
#include <cuda_runtime.h>
#include <cuda_fp16.h>
#include <math.h>
#include <stdint.h>

// ---------------- problem constants ----------------
#define NB    4
#define SEQ   1024
#define HDIM  1024
#define NHEAD 16
#define HEADD 64
#define NLAYER 12
#define MLPD  4096
#define DESM  1280
#define NROWS (NB*SEQ)   // 4096
#define NVOC  26

// ---------------- scratch (static device; no allocs allowed) ----------------
__device__ float  g_x   [NROWS*HDIM];
__device__ float  g_h   [NROWS*HDIM];      // fp32 (final head path)
__device__ __half g_h16 [NROWS*HDIM];      // fp16 ln-mod output (GEMM A)
__device__ __half g_qkv16[NROWS*3*HDIM];   // fp16 qkv
__device__ __half g_o16 [NROWS*HDIM];      // fp16 attention output
__device__ __half g_mid16[NROWS*MLPD];     // fp16 gelu output
__device__ float  g_tsin[NB*256];
__device__ float  g_lsin[NB*128];
__device__ float  g_tb  [NB*HDIM];
__device__ float  g_temb[NB*HDIM];
__device__ float  g_lb  [NB*HDIM];
__device__ float  g_lemb[NB*HDIM];
__device__ float  g_csilu[NB*HDIM];
__device__ float  g_modsAll[NLAYER*NB*6*HDIM];
__device__ float  g_fmods[NB*2*HDIM];
__device__ float  g_ropec[SEQ*32];
__device__ float  g_ropes[SEQ*32];

// fp16 pre-converted GEMM operands (row-major)
__device__ __half g_xt16  [NROWS*DESM];
__device__ __half g_w_proj[DESM*HDIM];
__device__ __half g_w_qkv [NLAYER*HDIM*3*HDIM];
__device__ __half g_w_ap  [NLAYER*HDIM*HDIM];
__device__ __half g_w_m1  [NLAYER*HDIM*MLPD];
__device__ __half g_w_m2  [NLAYER*MLPD*HDIM];

// ---------------- small helpers ----------------
__device__ __forceinline__ float siluf(float x){ return x / (1.0f + __expf(-x)); }
__device__ __forceinline__ float geluf(float x){
    float u = 0.7978845608028654f*(x + 0.044715f*x*x*x);
    float t = 1.0f - 2.0f/(__expf(2.0f*u) + 1.0f);
    return 0.5f*x*(1.0f + t);
}
__device__ __forceinline__ uint32_t smem_u32(const void* p){
    return (uint32_t)__cvta_generic_to_shared(p);
}
__device__ __forceinline__ uint32_t h2pack(float a, float b){
    __half2 h = __floats2half2_rn(a, b);
    return *(uint32_t*)&h;
}
__device__ __forceinline__ void ldsm_x4(uint32_t& r0, uint32_t& r1, uint32_t& r2,
                                        uint32_t& r3, uint32_t addr)
{
    asm volatile("ldmatrix.sync.aligned.m8n8.x4.shared.b16 {%0,%1,%2,%3}, [%4];"
                 : "=r"(r0), "=r"(r1), "=r"(r2), "=r"(r3) : "r"(addr));
}
__device__ __forceinline__ void ldsm_x4t(uint32_t& r0, uint32_t& r1, uint32_t& r2,
                                         uint32_t& r3, uint32_t addr)
{
    asm volatile("ldmatrix.sync.aligned.m8n8.x4.trans.shared.b16 {%0,%1,%2,%3}, [%4];"
                 : "=r"(r0), "=r"(r1), "=r"(r2), "=r"(r3) : "r"(addr));
}
__device__ __forceinline__ void ldsm_x2t(uint32_t& r0, uint32_t& r1, uint32_t addr)
{
    asm volatile("ldmatrix.sync.aligned.m8n8.x2.trans.shared.b16 {%0,%1}, [%2];"
                 : "=r"(r0), "=r"(r1) : "r"(addr));
}
__device__ __forceinline__ void mma_f16(float& d0, float& d1, float& d2, float& d3,
    uint32_t a0, uint32_t a1, uint32_t a2, uint32_t a3, uint32_t b0, uint32_t b1)
{
    asm volatile("mma.sync.aligned.m16n8k16.row.col.f32.f16.f16.f32 "
        "{%0,%1,%2,%3}, {%4,%5,%6,%7}, {%8,%9}, {%0,%1,%2,%3};"
        : "+f"(d0), "+f"(d1), "+f"(d2), "+f"(d3)
        : "r"(a0), "r"(a1), "r"(a2), "r"(a3), "r"(b0), "r"(b1));
}

// ---------------- fp32 -> fp16 conversion (once per launch) ----------------
__global__ void f16_conv_kernel(const float4* __restrict__ src,
                                uint2* __restrict__ dst, int n4)
{
    int i = blockIdx.x*blockDim.x + threadIdx.x;
    int stride = gridDim.x*blockDim.x;
    for (; i < n4; i += stride) {
        float4 v = src[i];
        uint2 u;
        u.x = h2pack(v.x, v.y);
        u.y = h2pack(v.z, v.w);
        dst[i] = u;
    }
}

// ---------------- embeddings ----------------
__global__ void embed_kernel(const int* __restrict__ t, const int* __restrict__ Lt,
                             const int* __restrict__ Tv)
{
    int b = blockIdx.x;
    int i = threadIdx.x; // 128 threads
    float tn = (float)t[b] / (float)Tv[0];
    float f = expf(-logf(10000.0f) * (float)i / 128.0f);
    float a = tn * f;
    g_tsin[b*256 + i]       = cosf(a);
    g_tsin[b*256 + 128 + i] = sinf(a);
    if (i < 64) {
        float fl = expf(-logf(10000.0f) * (float)i / 64.0f);
        float al = (float)Lt[b] * fl;
        g_lsin[b*128 + i]      = cosf(al);
        g_lsin[b*128 + 64 + i] = sinf(al);
    }
}

__global__ void smallmm_kernel(const float* __restrict__ in, const float* __restrict__ w,
                               const float* __restrict__ bias, float* __restrict__ out,
                               int M, int K, int N, int act)
{
    int idx = blockIdx.x*blockDim.x + threadIdx.x;
    if (idx >= M*N) return;
    int m = idx / N, n = idx % N;
    float s = bias[n];
    const float* ip = in + (size_t)m*K;
    const float* wp = w + n;
    for (int k = 0; k < K; k += 4) {
        float4 iv = *(const float4*)(ip + k);
        s += iv.x * wp[(size_t)(k+0)*N];
        s += iv.y * wp[(size_t)(k+1)*N];
        s += iv.z * wp[(size_t)(k+2)*N];
        s += iv.w * wp[(size_t)(k+3)*N];
    }
    if (act == 1) s = siluf(s);
    out[idx] = s;
}

__global__ void ada_all_kernel(const float* __restrict__ aw, const float* __restrict__ ab)
{
    int idx = blockIdx.x*blockDim.x + threadIdx.x;
    if (idx >= NLAYER*NB*6*HDIM) return;
    int n = idx % (6*HDIM);
    int rest = idx / (6*HDIM);
    int b = rest & 3;
    int l = rest >> 2;
    const float* w = aw + (size_t)l*HDIM*6*HDIM + n;
    const float* c = g_csilu + b*HDIM;
    float s = ab[l*6*HDIM + n];
    #pragma unroll 4
    for (int k = 0; k < HDIM; k++) s += c[k] * w[(size_t)k*6*HDIM];
    g_modsAll[idx] = s;
}

__global__ void csilu_kernel()
{
    int idx = blockIdx.x*blockDim.x + threadIdx.x;
    if (idx >= NB*HDIM) return;
    float c = g_temb[idx] + g_lemb[idx];
    g_csilu[idx] = siluf(c);
}

__global__ void rope_table_kernel()
{
    int idx = blockIdx.x*blockDim.x + threadIdx.x;
    if (idx >= SEQ*32) return;
    int pos = idx >> 5, m = idx & 31;
    float f = expf(-logf(10000.0f) * (float)(2*m) / 64.0f);
    float a = (float)pos * f;
    g_ropec[idx] = cosf(a);
    g_ropes[idx] = sinf(a);
}

// ---------------- layernorm + modulate ----------------
__global__ void __launch_bounds__(256) ln_mod_kernel(const float* __restrict__ x,
                                                     const float* __restrict__ mods,
                                                     int mstride, int sh_off, int sc_off,
                                                     void* __restrict__ outv, int fmt16)
{
    __shared__ float red1[8];
    __shared__ float red2[8];
    int row = blockIdx.x;
    int b   = row >> 10;
    int tid = threadIdx.x;
    int lane = tid & 31, wid = tid >> 5;
    const float* xr = x + (size_t)row*HDIM;
    float4 v = *(const float4*)(xr + tid*4);
    float s = v.x + v.y + v.z + v.w;
    #pragma unroll
    for (int off = 16; off > 0; off >>= 1) s += __shfl_xor_sync(0xffffffffu, s, off);
    if (lane == 0) red1[wid] = s;
    __syncthreads();
    float mu = (red1[0]+red1[1]+red1[2]+red1[3]+red1[4]+red1[5]+red1[6]+red1[7])
               * (1.0f/1024.0f);
    float d0=v.x-mu, d1=v.y-mu, d2=v.z-mu, d3=v.w-mu;
    float q = d0*d0 + d1*d1 + d2*d2 + d3*d3;
    #pragma unroll
    for (int off = 16; off > 0; off >>= 1) q += __shfl_xor_sync(0xffffffffu, q, off);
    if (lane == 0) red2[wid] = q;
    __syncthreads();
    float var = (red2[0]+red2[1]+red2[2]+red2[3]+red2[4]+red2[5]+red2[6]+red2[7])
                * (1.0f/1024.0f);
    float rs  = rsqrtf(var + 1e-6f);
    int c = tid*4;
    float4 sc = *(const float4*)(mods + (size_t)b*mstride + sc_off + c);
    float4 sh = *(const float4*)(mods + (size_t)b*mstride + sh_off + c);
    float o0 = d0*rs*(1.0f+sc.x) + sh.x;
    float o1 = d1*rs*(1.0f+sc.y) + sh.y;
    float o2 = d2*rs*(1.0f+sc.z) + sh.z;
    float o3 = d3*rs*(1.0f+sc.w) + sh.w;
    if (fmt16) {
        uint2 u; u.x = h2pack(o0, o1); u.y = h2pack(o2, o3);
        *(uint2*)((__half*)outv + (size_t)row*HDIM + c) = u;
    } else {
        *(float4*)((float*)outv + (size_t)row*HDIM + c) = make_float4(o0,o1,o2,o3);
    }
}

// ---------------- fp16 tensor-core GEMM (exact R9 structure) ----------------
// MODE 0: C(fp32) = acc + bias
// MODE 1: C(fp16) = gelu(acc + bias)
// MODE 2: C(fp32) = resid + gate * (acc + bias)
// MODE 3: C(fp16) = acc + bias
template<int MODE>
__global__ void __launch_bounds__(256, 2) gemm_f16_kernel(
    const __half* __restrict__ A, const __half* __restrict__ W,
    const float* __restrict__ bias, void* __restrict__ Cv,
    int M, int N, int K,
    const float* __restrict__ resid, const float* __restrict__ gate,
    int g_off, int g_stride)
{
    __shared__ __align__(16) __half As[2][4096];
    __shared__ __align__(16) __half Bs[2][4096];

    const int tid = threadIdx.x;
    const int ln  = tid & 31;
    const int wp  = tid >> 5;
    const int wm  = wp >> 2;
    const int wn  = wp & 3;
    const int bm  = blockIdx.y * 128, bn = blockIdx.x * 128;

    float acc[4][4][4];
    #pragma unroll
    for (int i = 0; i < 4; i++)
        #pragma unroll
        for (int j = 0; j < 4; j++)
            #pragma unroll
            for (int c = 0; c < 4; c++) acc[i][j][c] = 0.0f;

    const int idA0 = tid, idA1 = tid + 256;
    const int arA0 = idA0 >> 2, tkA0 = idA0 & 3;
    const int arA1 = idA1 >> 2, tkA1 = idA1 & 3;
    const int brB0 = idA0 >> 4, ntB0 = idA0 & 15;
    const int brB1 = idA1 >> 4, ntB1 = idA1 & 15;

    uint4 pa[2], pb[2];
    const int nkt = K >> 5;

    pa[0] = *(const uint4*)(A + (size_t)(bm+arA0)*K + tkA0*8);
    pa[1] = *(const uint4*)(A + (size_t)(bm+arA1)*K + tkA1*8);
    pb[0] = *(const uint4*)(W + (size_t)brB0*N + bn + ntB0*8);
    pb[1] = *(const uint4*)(W + (size_t)brB1*N + bn + ntB1*8);

    #define STORE_TILE(BUF)                                                      \
    {                                                                            \
        {   int tile = ((arA0>>3)<<2) + tkA0;                                    \
            int row  = (arA0&7) ^ ((tkA0<<1)&7);                                 \
            *(uint4*)&As[BUF][tile*64 + row*8] = pa[0];                          \
            tile = ((arA1>>3)<<2) + tkA1;                                        \
            row  = (arA1&7) ^ ((tkA1<<1)&7);                                     \
            *(uint4*)&As[BUF][tile*64 + row*8] = pa[1];                          \
            tile = ((brB0>>3)<<4) + ntB0;                                        \
            row  = (brB0&7) ^ (ntB0&7);                                          \
            *(uint4*)&Bs[BUF][tile*64 + row*8] = pb[0];                          \
            tile = ((brB1>>3)<<4) + ntB1;                                        \
            row  = (brB1&7) ^ (ntB1&7);                                          \
            *(uint4*)&Bs[BUF][tile*64 + row*8] = pb[1];                          \
        }                                                                        \
    }

    STORE_TILE(0);
    __syncthreads();

    for (int kt = 0; kt < nkt; kt++) {
        const int cur = kt & 1;
        if (kt + 1 < nkt) {
            const __half* Ak = A + (size_t)(kt+1)*32;
            const __half* Wk = W + (size_t)(kt+1)*32*N;
            pa[0] = *(const uint4*)(Ak + (size_t)(bm+arA0)*K + tkA0*8);
            pa[1] = *(const uint4*)(Ak + (size_t)(bm+arA1)*K + tkA1*8);
            pb[0] = *(const uint4*)(Wk + (size_t)brB0*N + bn + ntB0*8);
            pb[1] = *(const uint4*)(Wk + (size_t)brB1*N + bn + ntB1*8);
        }

        #pragma unroll
        for (int s = 0; s < 2; s++) {
            uint32_t a[4][4], b[4][2];
            const int sel = ln >> 3, tmo = sel & 1, tko_a = sel >> 1;
            const int tkA = 2*s + tko_a;
            const int rowA = (ln&7) ^ ((tkA<<1)&7);
            #pragma unroll
            for (int i = 0; i < 4; i++) {
                int tmb = wm*8 + i*2;
                int tile = (tmb + tmo)*4 + tkA;
                ldsm_x4(a[i][0], a[i][1], a[i][2], a[i][3],
                        smem_u32(&As[cur][tile*64 + rowA*8]));
            }
            const int lnm = ln & 15;
            const int tkB = 2*s + (lnm >> 3);
            #pragma unroll
            for (int j = 0; j < 4; j++) {
                int nt = wn*4 + j;
                int tile = tkB*16 + nt;
                int rowB = (lnm&7) ^ (nt&7);
                ldsm_x2t(b[j][0], b[j][1],
                         smem_u32(&Bs[cur][tile*64 + rowB*8]));
            }
            #pragma unroll
            for (int i = 0; i < 4; i++)
                #pragma unroll
                for (int j = 0; j < 4; j++)
                    mma_f16(acc[i][j][0],acc[i][j][1],acc[i][j][2],acc[i][j][3],
                            a[i][0],a[i][1],a[i][2],a[i][3], b[j][0],b[j][1]);
        }

        if (kt + 1 < nkt) STORE_TILE(cur ^ 1);
        __syncthreads();
    }
    #undef STORE_TILE

    float*  C   = (float*)Cv;
    __half* C16 = (__half*)Cv;
    const int g0 = ln >> 2, t0 = ln & 3;
    #pragma unroll
    for (int i = 0; i < 4; i++) {
        int m0 = bm + wm*64 + i*16 + g0;
        int m1 = m0 + 8;
        #pragma unroll
        for (int j = 0; j < 4; j++) {
            int n0 = bn + wn*32 + j*8 + t0*2;
            float2 bv = *(const float2*)(bias + n0);
            float v00 = acc[i][j][0] + bv.x;
            float v01 = acc[i][j][1] + bv.y;
            float v10 = acc[i][j][2] + bv.x;
            float v11 = acc[i][j][3] + bv.y;
            if (MODE == 1 || MODE == 3) {
                if (MODE == 1) { v00=geluf(v00); v01=geluf(v01); v10=geluf(v10); v11=geluf(v11); }
                uint32_t h0 = h2pack(v00, v01);
                uint32_t h1 = h2pack(v10, v11);
                *(uint32_t*)(C16 + (size_t)m0*N + n0) = h0;
                *(uint32_t*)(C16 + (size_t)m1*N + n0) = h1;
            } else {
                if (MODE == 2) {
                    float2 gv0 = *(const float2*)(gate + (size_t)(m0 >> 10)*g_stride + g_off + n0);
                    float2 gv1 = *(const float2*)(gate + (size_t)(m1 >> 10)*g_stride + g_off + n0);
                    float2 r0 = *(const float2*)(resid + (size_t)m0*N + n0);
                    float2 r1 = *(const float2*)(resid + (size_t)m1*N + n0);
                    v00 = r0.x + gv0.x*v00;  v01 = r0.y + gv0.y*v01;
                    v10 = r1.x + gv1.x*v10;  v11 = r1.y + gv1.y*v11;
                }
                *(float2*)(C + (size_t)m0*N + n0) = make_float2(v00, v01);
                *(float2*)(C + (size_t)m1*N + n0) = make_float2(v10, v11);
            }
        }
    }
}

// ---------------- fp16 tensor-core flash attention, BQ=128, 8 warps ----------
__global__ void __launch_bounds__(256) flash16_kernel(const __half* __restrict__ qkv,
                                                      __half* __restrict__ o)
{
    __shared__ __align__(16) __half Qs[8192];   // 128 x 64
    __shared__ __align__(16) __half Ks[4096];   // 64 x 64
    __shared__ __align__(16) __half Vs[4096];   // 64 x 64

    const int tid = threadIdx.x;
    const int ln  = tid & 31;
    const int w   = tid >> 5;                   // 0..7
    const int qt = blockIdx.x, h = blockIdx.y, b = blockIdx.z;
    const __half* base = qkv + (size_t)b*SEQ*3*HDIM + h*HEADD;

    const int g  = ln >> 3, rr = ln & 7;

    #pragma unroll
    for (int it = 0; it < 4; it++) {
        int id = tid + it*256;
        int pl = id >> 3;          // 0..127
        int ch = id & 7;
        int pos = qt*128 + pl;
        uint4 raw = *(const uint4*)(base + (size_t)pos*3*HDIM + ch*8);
        __half2* hp = (__half2*)&raw;
        int ci = pos*32 + ((ch&3)*8);
        float4 c0 = *(const float4*)(g_ropec + ci);
        float4 c1 = *(const float4*)(g_ropec + ci + 4);
        float4 s0 = *(const float4*)(g_ropes + ci);
        float4 s1 = *(const float4*)(g_ropes + ci + 4);
        float cc[8] = {c0.x,c0.y,c0.z,c0.w,c1.x,c1.y,c1.z,c1.w};
        float ss[8] = {s0.x,s0.y,s0.z,s0.w,s1.x,s1.y,s1.z,s1.w};
        uint4 outv;
        uint32_t* op = (uint32_t*)&outv;
        #pragma unroll
        for (int e = 0; e < 4; e++) {
            float x1 = __low2float(hp[e]), x2 = __high2float(hp[e]);
            float r1 = (x1*cc[2*e]   - x2*ss[2*e])  *0.125f;
            float r2 = (x2*cc[2*e+1] + x1*ss[2*e+1])*0.125f;
            op[e] = h2pack(r1, r2);
        }
        *(uint4*)&Qs[((pl>>3)*8 + ch)*64 + ((pl&7)^ch)*8] = outv;
    }

    float m_i[2], l_i[2], oa[8][4];
    m_i[0] = m_i[1] = -1e30f; l_i[0] = l_i[1] = 0.0f;
    #pragma unroll
    for (int j = 0; j < 8; j++)
        #pragma unroll
        for (int c = 0; c < 4; c++) oa[j][c] = 0.0f;

    for (int kt = 0; kt < SEQ/64; kt++) {
        __syncthreads();
        #pragma unroll
        for (int it = 0; it < 2; it++) {
            int id = tid + it*256;
            int pl = id >> 3;      // 0..63
            int ch = id & 7;
            int pos = kt*64 + pl;
            const __half* rowp = base + (size_t)pos*3*HDIM;
            uint4 raw = *(const uint4*)(rowp + HDIM + ch*8);
            __half2* hp = (__half2*)&raw;
            int ci = pos*32 + ((ch&3)*8);
            float4 c0 = *(const float4*)(g_ropec + ci);
            float4 c1 = *(const float4*)(g_ropec + ci + 4);
            float4 s0 = *(const float4*)(g_ropes + ci);
            float4 s1 = *(const float4*)(g_ropes + ci + 4);
            float cc[8] = {c0.x,c0.y,c0.z,c0.w,c1.x,c1.y,c1.z,c1.w};
            float ss[8] = {s0.x,s0.y,s0.z,s0.w,s1.x,s1.y,s1.z,s1.w};
            uint4 outv;
            uint32_t* op = (uint32_t*)&outv;
            #pragma unroll
            for (int e = 0; e < 4; e++) {
                float x1 = __low2float(hp[e]), x2 = __high2float(hp[e]);
                float r1 = x1*cc[2*e]   - x2*ss[2*e];
                float r2 = x2*cc[2*e+1] + x1*ss[2*e+1];
                op[e] = h2pack(r1, r2);
            }
            int dst = ((pl>>3)*8 + ch)*64 + ((pl&7)^ch)*8;
            *(uint4*)&Ks[dst] = outv;
            *(uint4*)&Vs[dst] = *(const uint4*)(rowp + 2*HDIM + ch*8);
        }
        __syncthreads();

        float sacc[8][4];
        #pragma unroll
        for (int j = 0; j < 8; j++)
            #pragma unroll
            for (int c = 0; c < 4; c++) sacc[j][c] = 0.0f;

        #pragma unroll
        for (int ks = 0; ks < 4; ks++) {
            const int dt0 = ks*2;
            uint32_t a0,a1,a2,a3;
            {
                int pt = w*2 + (g&1), dt = dt0 + (g>>1);
                ldsm_x4(a0,a1,a2,a3,
                        smem_u32(&Qs[(pt*8+dt)*64 + (rr^dt)*8]));
            }
            #pragma unroll
            for (int nb2 = 0; nb2 < 4; nb2++) {
                uint32_t b0,b1,b2,b3;
                int pt = nb2*2 + (g>>1), dt = dt0 + (g&1);
                ldsm_x4(b0,b1,b2,b3,
                        smem_u32(&Ks[(pt*8+dt)*64 + (rr^dt)*8]));
                mma_f16(sacc[nb2*2][0],sacc[nb2*2][1],sacc[nb2*2][2],sacc[nb2*2][3],
                        a0,a1,a2,a3, b0,b1);
                mma_f16(sacc[nb2*2+1][0],sacc[nb2*2+1][1],sacc[nb2*2+1][2],sacc[nb2*2+1][3],
                        a0,a1,a2,a3, b2,b3);
            }
        }

        float mx0 = -1e30f, mx1 = -1e30f;
        #pragma unroll
        for (int j = 0; j < 8; j++) {
            mx0 = fmaxf(mx0, fmaxf(sacc[j][0], sacc[j][1]));
            mx1 = fmaxf(mx1, fmaxf(sacc[j][2], sacc[j][3]));
        }
        mx0 = fmaxf(mx0, __shfl_xor_sync(0xffffffffu, mx0, 1));
        mx0 = fmaxf(mx0, __shfl_xor_sync(0xffffffffu, mx0, 2));
        mx1 = fmaxf(mx1, __shfl_xor_sync(0xffffffffu, mx1, 1));
        mx1 = fmaxf(mx1, __shfl_xor_sync(0xffffffffu, mx1, 2));
        float mn0 = fmaxf(m_i[0], mx0), mn1 = fmaxf(m_i[1], mx1);
        float al0 = __expf(m_i[0] - mn0), al1 = __expf(m_i[1] - mn1);
        float sum0 = 0.0f, sum1 = 0.0f;
        #pragma unroll
        for (int j = 0; j < 8; j++) {
            sacc[j][0] = __expf(sacc[j][0] - mn0);
            sacc[j][1] = __expf(sacc[j][1] - mn0);
            sacc[j][2] = __expf(sacc[j][2] - mn1);
            sacc[j][3] = __expf(sacc[j][3] - mn1);
            sum0 += sacc[j][0] + sacc[j][1];
            sum1 += sacc[j][2] + sacc[j][3];
        }
        sum0 += __shfl_xor_sync(0xffffffffu, sum0, 1);
        sum0 += __shfl_xor_sync(0xffffffffu, sum0, 2);
        sum1 += __shfl_xor_sync(0xffffffffu, sum1, 1);
        sum1 += __shfl_xor_sync(0xffffffffu, sum1, 2);
        l_i[0] = l_i[0]*al0 + sum0;
        l_i[1] = l_i[1]*al1 + sum1;
        m_i[0] = mn0; m_i[1] = mn1;
        #pragma unroll
        for (int j = 0; j < 8; j++) {
            oa[j][0] *= al0; oa[j][1] *= al0;
            oa[j][2] *= al1; oa[j][3] *= al1;
        }

        uint32_t pf[8][2];
        #pragma unroll
        for (int j = 0; j < 8; j++) {
            pf[j][0] = h2pack(sacc[j][0], sacc[j][1]);
            pf[j][1] = h2pack(sacc[j][2], sacc[j][3]);
        }

        #pragma unroll
        for (int ks = 0; ks < 4; ks++) {
            const int pt0 = ks*2;
            uint32_t a0 = pf[2*ks][0], a1 = pf[2*ks][1];
            uint32_t a2 = pf[2*ks+1][0], a3 = pf[2*ks+1][1];
            #pragma unroll
            for (int nb2 = 0; nb2 < 4; nb2++) {
                uint32_t b0,b1,b2,b3;
                int pt = pt0 + (g&1), dt = nb2*2 + (g>>1);
                ldsm_x4t(b0,b1,b2,b3,
                         smem_u32(&Vs[(pt*8+dt)*64 + (rr^dt)*8]));
                mma_f16(oa[nb2*2][0],oa[nb2*2][1],oa[nb2*2][2],oa[nb2*2][3],
                        a0,a1,a2,a3, b0,b1);
                mma_f16(oa[nb2*2+1][0],oa[nb2*2+1][1],oa[nb2*2+1][2],oa[nb2*2+1][3],
                        a0,a1,a2,a3, b2,b3);
            }
        }
    }

    float inv0 = 1.0f / l_i[0], inv1 = 1.0f / l_i[1];
    int r0 = b*SEQ + qt*128 + w*16 + (ln>>2);
    int r1 = r0 + 8;
    __half* ob = o + h*HEADD;
    #pragma unroll
    for (int j = 0; j < 8; j++) {
        int col = j*8 + (ln&3)*2;
        *(uint32_t*)(ob + (size_t)r0*HDIM + col) = h2pack(oa[j][0]*inv0, oa[j][1]*inv0);
        *(uint32_t*)(ob + (size_t)r1*HDIM + col) = h2pack(oa[j][2]*inv1, oa[j][3]*inv1);
    }
}

// ---------------- host side ----------------
static void* symaddr(const void* sym)
{
    void* p = nullptr;
    cudaGetSymbolAddress(&p, sym);
    return p;
}

static void f16_conv(const float* src, __half* dst, size_t n)
{
    int n4 = (int)(n >> 2);
    int grid = (n4 + 255)/256; if (grid > 4096) grid = 4096;
    f16_conv_kernel<<<grid, 256>>>((const float4*)src, (uint2*)dst, n4);
}

extern "C" void kernel_launch(void* const* d_in, const int* in_sizes, int n_in,
                              void* d_out, int out_size)
{
    const float* x_tokens  = (const float*)d_in[0];
    const int*   L_target  = (const int*)  d_in[1];
    const int*   t_in      = (const int*)  d_in[2];
    const int*   T_in      = (const int*)  d_in[3];
    const float* proj_in_w = (const float*)d_in[4];
    const float* proj_in_b = (const float*)d_in[5];
    const float* t_w1 = (const float*)d_in[6];
    const float* t_b1 = (const float*)d_in[7];
    const float* t_w2 = (const float*)d_in[8];
    const float* t_b2 = (const float*)d_in[9];
    const float* l_w1 = (const float*)d_in[10];
    const float* l_b1 = (const float*)d_in[11];
    const float* l_w2 = (const float*)d_in[12];
    const float* l_b2 = (const float*)d_in[13];
    const float* qkv_w = (const float*)d_in[14];
    const float* qkv_b = (const float*)d_in[15];
    const float* attn_proj_w = (const float*)d_in[16];
    const float* attn_proj_b = (const float*)d_in[17];
    const float* mlp_w1 = (const float*)d_in[18];
    const float* mlp_b1 = (const float*)d_in[19];
    const float* mlp_w2 = (const float*)d_in[20];
    const float* mlp_b2 = (const float*)d_in[21];
    const float* ada_w  = (const float*)d_in[22];
    const float* ada_b  = (const float*)d_in[23];
    const float* fin_ada_w = (const float*)d_in[24];
    const float* fin_ada_b = (const float*)d_in[25];
    const float* fin_w = (const float*)d_in[26];
    const float* fin_b = (const float*)d_in[27];
    float* out = (float*)d_out;

    float*  px    = (float*) symaddr(g_x);
    float*  ph    = (float*) symaddr(g_h);
    __half* ph16  = (__half*)symaddr(g_h16);
    __half* pqkv16= (__half*)symaddr(g_qkv16);
    __half* po16  = (__half*)symaddr(g_o16);
    __half* pmid16= (__half*)symaddr(g_mid16);
    float*  ptsin = (float*) symaddr(g_tsin);
    float*  plsin = (float*) symaddr(g_lsin);
    float*  ptb   = (float*) symaddr(g_tb);
    float*  ptemb = (float*) symaddr(g_temb);
    float*  plb   = (float*) symaddr(g_lb);
    float*  plemb = (float*) symaddr(g_lemb);
    float*  pcs   = (float*) symaddr(g_csilu);
    float*  pmodsAll = (float*)symaddr(g_modsAll);
    float*  pfmods= (float*) symaddr(g_fmods);
    __half* pxt16 = (__half*)symaddr(g_xt16);
    __half* pwproj= (__half*)symaddr(g_w_proj);
    __half* pwqkv = (__half*)symaddr(g_w_qkv);
    __half* pwap  = (__half*)symaddr(g_w_ap);
    __half* pwm1  = (__half*)symaddr(g_w_m1);
    __half* pwm2  = (__half*)symaddr(g_w_m2);

    // ---- pre-convert fp16 GEMM operands ----
    f16_conv(x_tokens,    pxt16, (size_t)NROWS*DESM);
    f16_conv(proj_in_w,   pwproj,(size_t)DESM*HDIM);
    f16_conv(qkv_w,       pwqkv, (size_t)NLAYER*HDIM*3*HDIM);
    f16_conv(attn_proj_w, pwap,  (size_t)NLAYER*HDIM*HDIM);
    f16_conv(mlp_w1,      pwm1,  (size_t)NLAYER*HDIM*MLPD);
    f16_conv(mlp_w2,      pwm2,  (size_t)NLAYER*MLPD*HDIM);

    // ---- conditioning path ----
    embed_kernel<<<NB, 128>>>(t_in, L_target, T_in);
    smallmm_kernel<<<(NB*HDIM+255)/256, 256>>>(ptsin, t_w1, t_b1, ptb,   NB, 256,  HDIM, 1);
    smallmm_kernel<<<(NB*HDIM+255)/256, 256>>>(ptb,   t_w2, t_b2, ptemb, NB, HDIM, HDIM, 0);
    smallmm_kernel<<<(NB*HDIM+255)/256, 256>>>(plsin, l_w1, l_b1, plb,   NB, 128,  HDIM, 1);
    smallmm_kernel<<<(NB*HDIM+255)/256, 256>>>(plb,   l_w2, l_b2, plemb, NB, HDIM, HDIM, 0);
    csilu_kernel<<<(NB*HDIM+255)/256, 256>>>();
    rope_table_kernel<<<(SEQ*32+255)/256, 256>>>();
    ada_all_kernel<<<(NLAYER*NB*6*HDIM+255)/256, 256>>>(ada_w, ada_b);

    // ---- input projection ----
    gemm_f16_kernel<0><<<dim3(HDIM/128, NROWS/128), 256>>>(
        pxt16, pwproj, proj_in_b, px, NROWS, HDIM, DESM,
        nullptr, nullptr, 0, 0);

    // ---- transformer blocks ----
    for (int l = 0; l < NLAYER; l++) {
        float* pmods = pmodsAll + (size_t)l*NB*6*HDIM;

        // --- attention half ---
        ln_mod_kernel<<<NROWS, 256>>>(px, pmods, 6*HDIM, 0, HDIM, ph16, 1);
        gemm_f16_kernel<3><<<dim3(3*HDIM/128, NROWS/128), 256>>>(
            ph16, pwqkv + (size_t)l*HDIM*3*HDIM, qkv_b + (size_t)l*3*HDIM, pqkv16,
            NROWS, 3*HDIM, HDIM, nullptr, nullptr, 0, 0);
        flash16_kernel<<<dim3(SEQ/128, NHEAD, NB), 256>>>(pqkv16, po16);
        gemm_f16_kernel<2><<<dim3(HDIM/128, NROWS/128), 256>>>(
            po16, pwap + (size_t)l*HDIM*HDIM, attn_proj_b + (size_t)l*HDIM, px,
            NROWS, HDIM, HDIM, px, pmods, 2*HDIM, 6*HDIM);

        // --- mlp half ---
        ln_mod_kernel<<<NROWS, 256>>>(px, pmods, 6*HDIM, 3*HDIM, 4*HDIM, ph16, 1);
        gemm_f16_kernel<1><<<dim3(MLPD/128, NROWS/128), 256>>>(
            ph16, pwm1 + (size_t)l*HDIM*MLPD, mlp_b1 + (size_t)l*MLPD, pmid16,
            NROWS, MLPD, HDIM, nullptr, nullptr, 0, 0);
        gemm_f16_kernel<2><<<dim3(HDIM/128, NROWS/128), 256>>>(
            pmid16, pwm2 + (size_t)l*MLPD*HDIM, mlp_b2 + (size_t)l*HDIM, px,
            NROWS, HDIM, MLPD, px, pmods, 5*HDIM, 6*HDIM);
    }

    // ---- final head ----
    smallmm_kernel<<<(NB*2*HDIM+255)/256, 256>>>(pcs, fin_ada_w, fin_ada_b, pfmods,
                                                 NB, HDIM, 2*HDIM, 0);
    ln_mod_kernel<<<NROWS, 256>>>(px, pfmods, 2*HDIM, 0, HDIM, ph, 0);
    smallmm_kernel<<<(NROWS*NVOC+255)/256, 256>>>(ph, fin_w, fin_b, out,
                                                  NROWS, HDIM, NVOC, 0);
}